// round 3
// baseline (speedup 1.0000x reference)
#include <cuda_runtime.h>
#include <cuda_bf16.h>

// PositionalEmbedding: out[t] = x[t] + pe_flat[t mod 2^20], B=32,C=256,H=64,W=64.
// pe computed in [h,w,ch] order, raw-reshaped onto [ch,h,w].
//
// Structure: 2^19 threads, each owns 8 float8 (256-bit) slots at a stride of
// 2^22 elements (multiple of M_BATCH=2^20), so the thread's pe 8-vector is
// loop-invariant: compute once, then stream with 256-bit LDG/STG (sm_100+).

#define N_TOTAL  (32 * 256 * 64 * 64)   // 33,554,432 elements
#define M_BATCH  (256 * 64 * 64)        // 1,048,576 = 2^20
#define NTHREADS (N_TOTAL / 8 / 8)      // 524,288 = 2^19 threads
#define QSTRIDE8 (N_TOTAL / 8 / 8)      // stride in float8 units per iter

__device__ __forceinline__ void ldg256(const float* p, float v[8]) {
    asm volatile(
        "ld.global.v8.f32 {%0,%1,%2,%3,%4,%5,%6,%7}, [%8];"
        : "=f"(v[0]), "=f"(v[1]), "=f"(v[2]), "=f"(v[3]),
          "=f"(v[4]), "=f"(v[5]), "=f"(v[6]), "=f"(v[7])
        : "l"(p));
}

__device__ __forceinline__ void stg256(float* p, const float v[8]) {
    asm volatile(
        "st.global.v8.f32 [%0], {%1,%2,%3,%4,%5,%6,%7,%8};"
        :: "l"(p),
           "f"(v[0]), "f"(v[1]), "f"(v[2]), "f"(v[3]),
           "f"(v[4]), "f"(v[5]), "f"(v[6]), "f"(v[7])
        : "memory");
}

__global__ __launch_bounds__(256)
void pe_add_kernel(const float* __restrict__ x,
                   const float* __restrict__ Wt,
                   const float* __restrict__ bias,
                   float* __restrict__ out)
{
    const int gid = blockIdx.x * 256 + threadIdx.x;   // 0 .. 2^19-1

    // First element this thread touches; (t mod 2^20) is invariant under the
    // 2^22-element iteration stride, so (i, j, c) — and pe — are fixed.
    const int t  = gid << 3;                // multiple of 8
    const int tm = t & (M_BATCH - 1);
    const int i  = tm >> 14;                // row
    const int j  = (tm >> 8) & 63;          // col
    const int c  = t & 255;                 // channel base (multiple of 8)

    const float inv63 = 1.0f / 63.0f;
    const float u  = (float)j * inv63;
    const float v  = (float)i * inv63;
    const float mu = 1.0f - u;
    const float mv = 1.0f - v;

    const float4* W4 = reinterpret_cast<const float4*>(Wt);  // row per channel

    float pe[8];
    #pragma unroll
    for (int k = 0; k < 8; k++) {
        const float4 w = W4[c + k];
        pe[k] = fmaf(w.x, u, fmaf(w.y, v, fmaf(w.z, mu, fmaf(w.w, mv, bias[c + k]))));
    }

    const float* xp = x   + (size_t)gid * 8;
    float*       op = out + (size_t)gid * 8;
    const size_t stride_elts = (size_t)QSTRIDE8 * 8;

    // 8 iterations total: two passes of { 4 in-flight 256-bit loads,
    // then 4 256-bit stores }.
    #pragma unroll
    for (int half = 0; half < 2; half++) {
        float d[4][8];
        #pragma unroll
        for (int kk = 0; kk < 4; kk++)
            ldg256(xp + (half * 4 + kk) * stride_elts, d[kk]);
        #pragma unroll
        for (int kk = 0; kk < 4; kk++) {
            #pragma unroll
            for (int e = 0; e < 8; e++)
                d[kk][e] += pe[e];
            stg256(op + (half * 4 + kk) * stride_elts, d[kk]);
        }
    }
}

extern "C" void kernel_launch(void* const* d_in, const int* in_sizes, int n_in,
                              void* d_out, int out_size)
{
    const float* x  = (const float*)d_in[0];   // [32,256,64,64] f32
    const float* Wt = (const float*)d_in[1];   // [256,4] f32
    const float* b  = (const float*)d_in[2];   // [256] f32
    float* out = (float*)d_out;

    (void)in_sizes; (void)n_in; (void)out_size;

    // 2048 blocks x 256 threads = 2^19 threads, 8 float8s each.
    pe_add_kernel<<<2048, 256>>>(x, Wt, b, out);
}

// round 4
// speedup vs baseline: 1.1178x; 1.1178x over previous
#include <cuda_runtime.h>
#include <cuda_bf16.h>

// PositionalEmbedding: out[t] = x[t] + pe_flat[t mod 2^20], B=32,C=256,H=64,W=64.
// pe computed in [h,w,ch] order, raw-reshaped onto [ch,h,w].
//
// Structure: 2^21 threads (8192 x 256), each owns 4 float4 slots at a stride
// of 2^21 float4s = 2^23 elements (multiple of M_BATCH=2^20), so the thread's
// pe float4 is loop-invariant: compute once from W/b, then pure 128-bit
// stream: 4x LDG.128 in flight -> 4x (FADD x4, STG.128).

#define N_TOTAL  (32 * 256 * 64 * 64)   // 33,554,432 elements
#define M_BATCH  (256 * 64 * 64)        // 1,048,576 = 2^20
#define NTHREADS (N_TOTAL / 4 / 4)      // 2,097,152 = 2^21 threads
#define QSTRIDE  (N_TOTAL / 4 / 4)      // per-iter stride in float4 units

__global__ __launch_bounds__(256)
void pe_add_kernel(const float* __restrict__ x,
                   const float* __restrict__ Wt,
                   const float* __restrict__ bias,
                   float* __restrict__ out)
{
    const int gid = blockIdx.x * 256 + threadIdx.x;   // 0 .. 2^21-1

    // First element this thread touches. (t mod 2^20) is invariant under the
    // 2^23-element iteration stride, so (i, j, c) — and pe — are fixed.
    const int t  = gid << 2;                // multiple of 4
    const int tm = t & (M_BATCH - 1);
    const int i  = tm >> 14;                // row
    const int j  = (tm >> 8) & 63;          // col
    const int c  = t & 255;                 // channel base (multiple of 4)

    const float inv63 = 1.0f / 63.0f;
    const float u  = (float)j * inv63;
    const float v  = (float)i * inv63;
    const float mu = 1.0f - u;
    const float mv = 1.0f - v;

    const float4* W4 = reinterpret_cast<const float4*>(Wt);   // one row / channel
    const float4  bb = reinterpret_cast<const float4*>(bias)[c >> 2];

    float4 pe;
    {
        const float4 w0 = W4[c + 0];
        const float4 w1 = W4[c + 1];
        const float4 w2 = W4[c + 2];
        const float4 w3 = W4[c + 3];
        pe.x = fmaf(w0.x, u, fmaf(w0.y, v, fmaf(w0.z, mu, fmaf(w0.w, mv, bb.x))));
        pe.y = fmaf(w1.x, u, fmaf(w1.y, v, fmaf(w1.z, mu, fmaf(w1.w, mv, bb.y))));
        pe.z = fmaf(w2.x, u, fmaf(w2.y, v, fmaf(w2.z, mu, fmaf(w2.w, mv, bb.z))));
        pe.w = fmaf(w3.x, u, fmaf(w3.y, v, fmaf(w3.w, mv, fmaf(w3.z, mu, bb.w))));
    }

    const float4* __restrict__ x4 = reinterpret_cast<const float4*>(x);
    float4* __restrict__ o4 = reinterpret_cast<float4*>(out);

    // 4 iterations, no bounds check (N/4 = 4 * 2^21 exactly).
    // All 4 LDG.128 issued back-to-back (MLP=4), then 4 STG.128.
    float4 xv[4];
    #pragma unroll
    for (int k = 0; k < 4; k++)
        xv[k] = __ldcs(&x4[gid + k * QSTRIDE]);

    #pragma unroll
    for (int k = 0; k < 4; k++) {
        float4 o;
        o.x = xv[k].x + pe.x;
        o.y = xv[k].y + pe.y;
        o.z = xv[k].z + pe.z;
        o.w = xv[k].w + pe.w;
        __stcs(&o4[gid + k * QSTRIDE], o);
    }
}

extern "C" void kernel_launch(void* const* d_in, const int* in_sizes, int n_in,
                              void* d_out, int out_size)
{
    const float* x  = (const float*)d_in[0];   // [32,256,64,64] f32
    const float* Wt = (const float*)d_in[1];   // [256,4] f32
    const float* b  = (const float*)d_in[2];   // [256] f32
    float* out = (float*)d_out;

    (void)in_sizes; (void)n_in; (void)out_size;

    // 8192 blocks x 256 threads = 2^21 threads, 4 float4s each.
    pe_add_kernel<<<8192, 256>>>(x, Wt, b, out);
}